// round 8
// baseline (speedup 1.0000x reference)
#include <cuda_runtime.h>

// Permutation: out[b,i,j,W,p,q] = x[b, 2i+p, 2j+q, W]   (k=2 unfold repack)
// x: (16, 64, 224, 224) fp32 -> pure streaming permutation, HBM-bound.
//
// R8 = R4 structure (one-shot grid, XOR-swizzled conflict-free smem,
// LDG.128 in / STG.128 out) with one change: stores use DEFAULT write-back
// policy instead of __stcs. Evict-first on the write stream forces L2 to
// drain dirty sectors eagerly in small batches; write-back lets L2 batch
// larger writeback bursts -> fewer DRAM R/W turnarounds. Loads stay __ldcs
// (streaming reads, keep L2 capacity for the write side).

#define H 224
#define W_DIM 224
#define C 64
#define JN 112          // h/2
#define IN 32           // c/2
#define W4 56           // W_DIM/4 float4 per row
#define THREADS 224     // 4 segments x 56 groups
#define GRID 14336      // 57344 segments / 4

__device__ __forceinline__ int sw(int f) { return f ^ ((f >> 3) & 7); }

__global__ void __launch_bounds__(THREADS) KernelActivation_perm8(
    const float4* __restrict__ x4, float4* __restrict__ out4)
{
    __shared__ float4 s[4 * W_DIM];     // 14336 B

    const int tid  = threadIdx.x;
    const int sl   = tid / W4;          // 0..3 local segment
    const int wg   = tid % W4;          // 0..55 float4 group in row
    const int seg4 = blockIdx.x * 4;
    const int seg  = seg4 + sl;

    const int j = seg % JN;
    const int t = seg / JN;
    const int i = t & (IN - 1);
    const int b = t >> 5;

    // x[b, 2i+p, 2j+q, :] rows (float4 units)
    const int base = ((b * C + 2 * i) * H + 2 * j) * W4 + wg;

    const float4 r00 = __ldcs(&x4[base]);                 // p=0 q=0
    const float4 r01 = __ldcs(&x4[base + W4]);            // p=0 q=1
    const float4 r10 = __ldcs(&x4[base + H * W4]);        // p=1 q=0
    const float4 r11 = __ldcs(&x4[base + H * W4 + W4]);   // p=1 q=1

    // STS: f = 4*tid + m, swizzled -> conflict-free
    const int f0 = 4 * tid;
    s[sw(f0 + 0)] = make_float4(r00.x, r01.x, r10.x, r11.x);
    s[sw(f0 + 1)] = make_float4(r00.y, r01.y, r10.y, r11.y);
    s[sw(f0 + 2)] = make_float4(r00.z, r01.z, r10.z, r11.z);
    s[sw(f0 + 3)] = make_float4(r00.w, r01.w, r10.w, r11.w);

    __syncthreads();

    // drain: contiguous 14336B block store, default write-back policy
    float4* dst = &out4[(long)seg4 * W_DIM];
#pragma unroll
    for (int m = 0; m < 4; m++) {
        const int f = m * THREADS + tid;
        dst[f] = s[sw(f)];
    }
}

extern "C" void kernel_launch(void* const* d_in, const int* in_sizes, int n_in,
                              void* d_out, int out_size)
{
    const float4* x4 = (const float4*)d_in[0];
    float4* out4 = (float4*)d_out;
    KernelActivation_perm8<<<GRID, THREADS>>>(x4, out4);
}

// round 9
// speedup vs baseline: 1.0247x; 1.0247x over previous
#include <cuda_runtime.h>

// Permutation: out[b,i,j,W,p,q] = x[b, 2i+p, 2j+q, W]   (k=2 unfold repack)
// x: (16, 64, 224, 224) fp32 -> pure streaming permutation, HBM-bound.
//
// R9: R4/R8 structure (one-shot grid, XOR-swizzled conflict-free smem,
// LDG.128 in / STG.128 out, streaming hints) at 2x block granularity:
// 8 segments per block, 448 threads, 7168 blocks. Halves per-block fixed
// overhead and doubles each block's contiguous store run to 28672B.
// All per-warp global access shapes identical to the proven R4 kernel.

#define H 224
#define W_DIM 224
#define C 64
#define JN 112          // h/2
#define IN 32           // c/2
#define W4 56           // W_DIM/4 float4 per row
#define SEGB 8          // segments per block
#define THREADS 448     // SEGB * W4
#define GRID 7168       // 57344 / SEGB

__device__ __forceinline__ int sw(int f) { return f ^ ((f >> 3) & 7); }

__global__ void __launch_bounds__(THREADS) KernelActivation_perm9(
    const float4* __restrict__ x4, float4* __restrict__ out4)
{
    __shared__ float4 s[SEGB * W_DIM];   // 28672 B

    const int tid  = threadIdx.x;
    const int sl   = tid / W4;           // 0..7 local segment
    const int wg   = tid % W4;           // 0..55 float4 group in row
    const int seg0 = blockIdx.x * SEGB;
    const int seg  = seg0 + sl;

    const int j = seg % JN;
    const int t = seg / JN;
    const int i = t & (IN - 1);
    const int b = t >> 5;

    // x[b, 2i+p, 2j+q, :] rows (float4 units)
    const int base = ((b * C + 2 * i) * H + 2 * j) * W4 + wg;

    const float4 r00 = __ldcs(&x4[base]);                 // p=0 q=0
    const float4 r01 = __ldcs(&x4[base + W4]);            // p=0 q=1
    const float4 r10 = __ldcs(&x4[base + H * W4]);        // p=1 q=0
    const float4 r11 = __ldcs(&x4[base + H * W4 + W4]);   // p=1 q=1

    // STS: f = 4*tid + m, swizzled -> conflict-free (same proof as R4:
    // swizzle only permutes within 8-float4 groups; stride-4 lanes land
    // on distinct banks after XOR of bits[5:3] into bits[2:0]).
    const int f0 = 4 * tid;
    s[sw(f0 + 0)] = make_float4(r00.x, r01.x, r10.x, r11.x);
    s[sw(f0 + 1)] = make_float4(r00.y, r01.y, r10.y, r11.y);
    s[sw(f0 + 2)] = make_float4(r00.z, r01.z, r10.z, r11.z);
    s[sw(f0 + 3)] = make_float4(r00.w, r01.w, r10.w, r11.w);

    __syncthreads();

    // drain: contiguous 28672B block store, LDS swizzled -> conflict-free
    float4* dst = &out4[(long)seg0 * W_DIM];
#pragma unroll
    for (int m = 0; m < 4; m++) {
        const int f = m * THREADS + tid;
        __stcs(&dst[f], s[sw(f)]);
    }
}

extern "C" void kernel_launch(void* const* d_in, const int* in_sizes, int n_in,
                              void* d_out, int out_size)
{
    const float4* x4 = (const float4*)d_in[0];
    float4* out4 = (float4*)d_out;
    KernelActivation_perm9<<<GRID, THREADS>>>(x4, out4);
}